// round 14
// baseline (speedup 1.0000x reference)
#include <cuda_runtime.h>

#define NQ 6
#define NF 4
#define NL 2
#define NS 64

// ---------- compile-time CNOT permutation tracking ----------
__host__ __device__ constexpr int cnot_map(int i, int c, int t) {
    return (i & (1 << (5 - c))) ? (i ^ (1 << (5 - t))) : i;
}

struct Perm { int m[NS]; };

__host__ __device__ constexpr Perm identity_perm() {
    Perm p{};
    for (int i = 0; i < NS; i++) p.m[i] = i;
    return p;
}

__host__ __device__ constexpr Perm ring_perm(Perm p) {
    for (int w = 0; w < NQ; w++) {
        Perm q{};
        for (int i = 0; i < NS; i++)
            q.m[i] = p.m[cnot_map(i, w, (w + 1) % NQ)];
        p = q;
    }
    return p;
}

// ---------- packed f32x2 helpers (sm_100+) ----------
typedef unsigned long long u64;

__device__ __forceinline__ u64 pk(float lo, float hi) {
    u64 r;
    asm("mov.b64 %0, {%1, %2};" : "=l"(r) : "f"(lo), "f"(hi));
    return r;
}
__device__ __forceinline__ void upk(u64 v, float& lo, float& hi) {
    asm("mov.b64 {%0, %1}, %2;" : "=f"(lo), "=f"(hi) : "l"(v));
}
__device__ __forceinline__ u64 f2mul(u64 a, u64 b) {
    u64 d;
    asm("mul.rn.f32x2 %0, %1, %2;" : "=l"(d) : "l"(a), "l"(b));
    return d;
}
__device__ __forceinline__ u64 f2fma(u64 a, u64 b, u64 c) {
    u64 d;
    asm("fma.rn.f32x2 %0, %1, %2, %3;" : "=l"(d) : "l"(a), "l"(b), "l"(c));
    return d;
}
__device__ __forceinline__ u64 f2add(u64 a, u64 b) {
    u64 d;
    asm("add.rn.f32x2 %0, %1, %2;" : "=l"(d) : "l"(a), "l"(b));
    return d;
}

// One thread = one sample. Packed state: V[idx] = (Re, Im) in one 64-bit reg pair.
// __launch_bounds__(64, 6): reg cap 170 (natural 172, so a 2-reg nudge, no spill
// cliff) -> 6 blocks/SM -> 888 resident -> effective waves 1.38 -> 1.15.
__global__ void __launch_bounds__(64, 6) qsim_kernel(const float* __restrict__ x,
                                                     const float* __restrict__ wts,
                                                     const float* __restrict__ ab,
                                                     float* __restrict__ out) {
    constexpr Perm P1 = ring_perm(identity_perm());  // after layer-1 CNOT ring
    constexpr Perm P2 = ring_perm(P1);               // after layer-2 CNOT ring

    // Weight-dependent coefficients in shared memory: zero persistent register
    // cost, broadcast LDS reads, no separate prep kernel.
    __shared__ u64   s_t[NL * NQ];    // (t, t),  t = tan(theta/2)
    __shared__ u64   s_nt[NL * NQ];   // (-t, -t)
    __shared__ float s_anc[4];        // ancilla Kronecker factors * C (cos product)

    if (threadIdx.x == 0) {
        float C = 1.0f;
#pragma unroll
        for (int i = 0; i < NL * NQ; i++) {
            float s, c;
            __sincosf(0.5f * wts[i], &s, &c);
            float t = __fdividef(s, c);
            // Last layer's RY on qubits 4,5 is dropped below (commutes with the
            // measured Z_0..Z_3), so exclude their cos factors from C too.
            if (!(i >= NQ + 4)) C *= c;
            s_t[i]  = pk(t, t);
            s_nt[i] = pk(-t, -t);
        }
        float ac0, as0, ac1, as1;
        __sincosf(0.5f * ab[0], &as0, &ac0);
        __sincosf(0.5f * ab[1], &as1, &ac1);
        s_anc[0] = ac0 * ac1 * C;
        s_anc[1] = ac0 * as1 * C;
        s_anc[2] = as0 * ac1 * C;
        s_anc[3] = as0 * as1 * C;
    }

    const int b = blockIdx.x * blockDim.x + threadIdx.x;

    // ---- per-thread x trig (overlaps with thread-0 smem prep) ----
    float4 xv = reinterpret_cast<const float4*>(x)[b];
    float xc[NF], xs[NF];
    __sincosf(0.5f * xv.x, &xs[0], &xc[0]);
    __sincosf(0.5f * xv.y, &xs[1], &xc[1]);
    __sincosf(0.5f * xv.z, &xs[2], &xc[2]);
    __sincosf(0.5f * xv.w, &xs[3], &xc[3]);

    // ---- initial product state ----
    // RX(x)|0> per encoded qubit -> magnitude Kronecker product, phase (-i)^k,
    // k = popcount over qubits 0..3; sign folded into the magnitude.
    float p2[4];
    p2[0] = xc[0] * xc[1];
    p2[1] = xc[0] * xs[1];
    p2[2] = xs[0] * xc[1];
    p2[3] = xs[0] * xs[1];

    float p4s[16];
#pragma unroll
    for (int n = 0; n < 16; n++) {
        const int k = ((n & 1) + ((n >> 1) & 1) + ((n >> 2) & 1) + ((n >> 3) & 1)) & 3;
        float f2 = (n & 2) ? xs[2] : xc[2];
        float f3 = (n & 1) ? xs[3] : xc[3];
        float v = p2[n >> 2] * f2 * f3;
        if (k == 1 || k == 2) v = -v;
        p4s[n] = v;
    }

    __syncthreads();  // smem coefficients ready

    float anc0 = s_anc[0], anc1 = s_anc[1], anc2 = s_anc[2], anc3 = s_anc[3];

    u64 V[NS];
#pragma unroll
    for (int idx = 0; idx < NS; idx++) {
        const int n = idx >> 2;
        const int m = idx & 3;
        const int k = ((n & 1) + ((n >> 1) & 1) + ((n >> 2) & 1) + ((n >> 3) & 1)) & 3;
        float a = (m == 0) ? anc0 : (m == 1) ? anc1 : (m == 2) ? anc2 : anc3;
        float mag = p4s[n] * a;
        V[idx] = (k & 1) ? pk(0.0f, mag) : pk(mag, 0.0f);
    }

    // ---- entangling layers: CNOT ring (free via perm) + tan-form RY sweep ----
    // RY = cos * [[1,-t],[t,1]]; cos factors pre-folded into anc via C.
    // Butterfly: v0' = v0 - t*v1 ; v1' = v1 + t*v0  -> 1 packed FMA per output.
    // Last layer: RY on qubits 4,5 commutes with Z_0..Z_3 -> skipped (exact).
#pragma unroll
    for (int l = 0; l < NL; l++) {
#pragma unroll
        for (int w = 0; w < NQ; w++) {
            if (l == NL - 1 && w >= 4) continue;
            const u64 tt  = s_t[l * NQ + w];
            const u64 ntt = s_nt[l * NQ + w];
            const int tb = 1 << (5 - w);
#pragma unroll
            for (int idx = 0; idx < NS; idx++) {
                if (!(idx & tb)) {
                    const int j = idx | tb;
                    const int a  = (l == 0) ? P1.m[idx] : P2.m[idx];
                    const int bb = (l == 0) ? P1.m[j]   : P2.m[j];
                    u64 v0 = V[a], v1 = V[bb];
                    V[a]  = f2fma(ntt, v1, v0);
                    V[bb] = f2fma(tt,  v0, v1);
                }
            }
        }
    }

    // ---- readout ----
    // p[idx] = (r^2, i^2) packed; reduce over the 4 ancilla states (idx&3) via
    // an FMA chain, then a partial Walsh tree -> the 4 <Z_w>.
    u64 c16[16];
#pragma unroll
    for (int n = 0; n < 16; n++) {
        const u64 q0 = V[P2.m[4 * n + 0]];
        const u64 q1 = V[P2.m[4 * n + 1]];
        const u64 q2 = V[P2.m[4 * n + 2]];
        const u64 q3 = V[P2.m[4 * n + 3]];
        c16[n] = f2fma(q0, q0, f2fma(q1, q1, f2fma(q2, q2, f2mul(q3, q3))));
    }

    const u64 m1 = pk(-1.0f, -1.0f);   // f2sub(a,b) = fma(b, -1, a)
#define F2SUB(a, bq) f2fma((bq), m1, (a))

    // n bits: bit3 = qubit0, bit2 = qubit1, bit1 = qubit2, bit0 = qubit3
    u64 eA[8], z3s;
    {
        u64 d[8];
#pragma unroll
        for (int k = 0; k < 8; k++) {
            eA[k] = f2add(c16[2 * k], c16[2 * k + 1]);
            d[k]  = F2SUB(c16[2 * k], c16[2 * k + 1]);
        }
        z3s = f2add(f2add(f2add(d[0], d[1]), f2add(d[2], d[3])),
                    f2add(f2add(d[4], d[5]), f2add(d[6], d[7])));
    }
    u64 eB[4], z2s;
    {
        u64 d[4];
#pragma unroll
        for (int k = 0; k < 4; k++) {
            eB[k] = f2add(eA[2 * k], eA[2 * k + 1]);
            d[k]  = F2SUB(eA[2 * k], eA[2 * k + 1]);
        }
        z2s = f2add(f2add(d[0], d[1]), f2add(d[2], d[3]));
    }
    u64 eC0 = f2add(eB[0], eB[1]);
    u64 eC1 = f2add(eB[2], eB[3]);
    u64 z1s = f2add(F2SUB(eB[0], eB[1]), F2SUB(eB[2], eB[3]));
    u64 z0s = F2SUB(eC0, eC1);

    float4 o;
    float lo, hi;
    upk(z0s, lo, hi); o.x = lo + hi;
    upk(z1s, lo, hi); o.y = lo + hi;
    upk(z2s, lo, hi); o.z = lo + hi;
    upk(z3s, lo, hi); o.w = lo + hi;
    reinterpret_cast<float4*>(out)[b] = o;
}

extern "C" void kernel_launch(void* const* d_in, const int* in_sizes, int n_in,
                              void* d_out, int out_size) {
    const float* x  = (const float*)d_in[0];   // (B, 4)
    const float* w  = (const float*)d_in[1];   // (2, 6)
    const float* ab = (const float*)d_in[2];   // (2,)

    int B = in_sizes[0] / NF;
    int threads = 64;
    int blocks = B / threads;  // 1024
    qsim_kernel<<<blocks, threads>>>(x, w, ab, (float*)d_out);
}